// round 4
// baseline (speedup 1.0000x reference)
#include <cuda_runtime.h>
#include <cstdint>

// FP8 (E4M3 bit-vector of 0.0/1.0 floats) -> FP32 bit-vector.
// In : 4194304 rows x 8 floats  [s, e3, e2, e1, e0, m2, m1, m0]
// Out: 4194304 rows x 32 floats [s, exp7..exp0, mant22..mant0]
// Only outputs 0..11 per row can be nonzero.
//
// Smem-staged so both global loads and stores are fully coalesced.
// R4: 512 rows/block (2 per thread) for deeper front-batched MLP and half the
// barrier count per byte; streaming cache hints (.cs) on the global streams.

#define TPB  256
#define RPB  512   // rows per block (2 per thread)

__device__ __forceinline__ uint32_t fp32_word(uint4 A, uint4 B)
{
    // 1.0f == 0x3F800000 -> test bit 29.
    uint32_t s = (A.x >> 29) & 1u;
    uint32_t e = ((A.y >> 26) & 8u) | ((A.z >> 27) & 4u) |
                 ((A.w >> 28) & 2u) | ((B.x >> 29) & 1u);
    uint32_t m = ((B.y >> 27) & 4u) | ((B.z >> 28) & 2u) |
                 ((B.w >> 29) & 1u);

    uint32_t expf, mant;
    if (e != 0u) {                 // normal (incl. NaN pattern, as reference)
        expf = e + 120u;
        mant = m << 20;
    } else if (m & 4u) {           // subnormal 1xx
        expf = 120u;
        mant = (m & 3u) << 21;
    } else if (m & 2u) {           // subnormal 01x
        expf = 119u;
        mant = (m & 1u) << 22;
    } else if (m != 0u) {          // subnormal 001
        expf = 118u;
        mant = 0u;
    } else {                       // true zero
        expf = 0u;
        mant = 0u;
    }
    return (s << 31) | (expf << 23) | mant;   // bits 19..0 == 0
}

template <bool FULL>
__global__ void __launch_bounds__(TPB)
fp8_to_fp32_bits_kernel(const uint4* __restrict__ in,
                        uint4* __restrict__ out,
                        int nrows)
{
    __shared__ uint4    s_in[2 * RPB];   // 512 rows x 32B = 16KB
    __shared__ uint32_t s_w[RPB];        // one fp32 bit-word per row (2KB)

    const int t = threadIdx.x;
    const size_t rowBase = (size_t)blockIdx.x * RPB;
    const int rowsHere = FULL ? RPB : min(RPB, nrows - (int)rowBase);

    // ---- Phase 1: front-batched coalesced loads (4 LDG.128/thread) ----
    const uint4* gin = in + rowBase * 2;
    #pragma unroll
    for (int k = 0; k < 4; k++) {
        int idx = k * TPB + t;
        if (FULL || idx < 2 * rowsHere)
            s_in[idx] = __ldcs(&gin[idx]);
    }
    __syncthreads();

    // ---- Phase 2: two rows per thread -> fp32 bit words ----
    #pragma unroll
    for (int k = 0; k < 2; k++) {
        int r = k * TPB + t;
        if (FULL || r < rowsHere)
            s_w[r] = fp32_word(s_in[2 * r], s_in[2 * r + 1]);
    }
    __syncthreads();

    // ---- Phase 3: coalesced streaming stores (contiguous 64KB/block) ----
    uint4* gout = out + rowBase * 8;
    const uint32_t ONE = 0x3F800000u;
    const int chunksHere = 8 * rowsHere;

    #pragma unroll
    for (int k = 0; k < 16; k++) {
        int idx  = k * TPB + t;
        if (!FULL && idx >= chunksHere) break;
        int row  = idx >> 3;           // which row this 16B chunk belongs to
        int part = idx & 7;            // which of the 8 chunks in the row
        uint4 v = make_uint4(0u, 0u, 0u, 0u);
        if (part < 3) {
            uint32_t w  = s_w[row];    // broadcast across the 8 lanes of a row
            int sh = 31 - part * 4;    // chunk0: 31..28, chunk1: 27..24, chunk2: 23..20
            v.x = ((w >> sh)       & 1u) * ONE;
            v.y = ((w >> (sh - 1)) & 1u) * ONE;
            v.z = ((w >> (sh - 2)) & 1u) * ONE;
            v.w = ((w >> (sh - 3)) & 1u) * ONE;
        }
        __stcs(&gout[idx], v);
    }
}

extern "C" void kernel_launch(void* const* d_in, const int* in_sizes, int n_in,
                              void* d_out, int out_size)
{
    const uint4* in  = (const uint4*)d_in[0];
    uint4*       out = (uint4*)d_out;
    int nrows = in_sizes[0] / 8;              // 4194304

    int fullBlocks = nrows / RPB;             // 8192
    int remRows    = nrows % RPB;

    if (fullBlocks > 0)
        fp8_to_fp32_bits_kernel<true><<<fullBlocks, TPB>>>(in, out, nrows);
    if (remRows > 0)
        fp8_to_fp32_bits_kernel<false><<<1, TPB>>>(
            in + (size_t)fullBlocks * RPB * 2,
            out + (size_t)fullBlocks * RPB * 8,
            remRows);
}

// round 5
// speedup vs baseline: 1.0024x; 1.0024x over previous
#include <cuda_runtime.h>
#include <cstdint>

// FP8 (E4M3 bit-vector of 0.0/1.0 floats) -> FP32 bit-vector.
// In : 4194304 rows x 8 floats  [s, e3, e2, e1, e0, m2, m1, m0]
// Out: 4194304 rows x 32 floats [s, exp7..exp0, mant22..mant0]
// Only outputs 0..11 per row can be nonzero.
//
// R5: no shared memory, no barriers. Each warp owns 32 consecutive rows:
// lane l computes the fp32 bit-word for row l in a register; the store loop
// broadcasts it to the 8 lanes writing that row via __shfl_sync. Loads cover
// a contiguous 2KB per warp; every STG.128 covers a contiguous 512B.

#define TPB 256
#define RPB 256   // rows per block (32 per warp, 8 warps)

__device__ __forceinline__ uint32_t fp32_word(uint4 A, uint4 B)
{
    // 1.0f == 0x3F800000 -> test bit 29.
    uint32_t s = (A.x >> 29) & 1u;
    uint32_t e = ((A.y >> 26) & 8u) | ((A.z >> 27) & 4u) |
                 ((A.w >> 28) & 2u) | ((B.x >> 29) & 1u);
    uint32_t m = ((B.y >> 27) & 4u) | ((B.z >> 28) & 2u) |
                 ((B.w >> 29) & 1u);

    uint32_t expf, mant;
    if (e != 0u) {                 // normal (incl. NaN pattern, as reference)
        expf = e + 120u;
        mant = m << 20;
    } else if (m & 4u) {           // subnormal 1xx
        expf = 120u;
        mant = (m & 3u) << 21;
    } else if (m & 2u) {           // subnormal 01x
        expf = 119u;
        mant = (m & 1u) << 22;
    } else if (m != 0u) {          // subnormal 001
        expf = 118u;
        mant = 0u;
    } else {                       // true zero
        expf = 0u;
        mant = 0u;
    }
    return (s << 31) | (expf << 23) | mant;   // bits 19..0 == 0
}

__global__ void __launch_bounds__(TPB)
fp8_full_kernel(const uint4* __restrict__ in, uint4* __restrict__ out)
{
    const int lane = threadIdx.x & 31;
    const int warp = threadIdx.x >> 5;
    const size_t warpRowBase = (size_t)blockIdx.x * RPB + warp * 32;

    // ---- Load: lane l reads row (warpRowBase + l): 2 x LDG.128.
    // Warp footprint: contiguous 2KB, all sectors used.
    const uint4* gin = in + warpRowBase * 2;
    uint4 A = gin[2 * lane];
    uint4 B = gin[2 * lane + 1];

    // ---- Compute: one fp32 bit-word per lane (row l).
    uint32_t w = fp32_word(A, B);

    // ---- Store: warp writes 32 rows x 128B = 4KB contiguous, 8 iterations.
    // Iteration k, lane l writes 16B chunk (k*32 + l); that chunk belongs to
    // row 4k + (l>>3), whose word lives in lane 4k + (l>>3).
    uint4* gout = out + warpRowBase * 8;
    const uint32_t ONE = 0x3F800000u;
    const int part = lane & 7;          // chunk index within the row
    const int rsel = lane >> 3;         // row-within-group offset

    #pragma unroll
    for (int k = 0; k < 8; k++) {
        uint32_t wr = __shfl_sync(0xFFFFFFFFu, w, 4 * k + rsel);
        uint4 v = make_uint4(0u, 0u, 0u, 0u);
        if (part < 3) {
            int sh = 31 - part * 4;     // chunk0: bits 31..28, 1: 27..24, 2: 23..20
            v.x = ((wr >> sh)       & 1u) * ONE;
            v.y = ((wr >> (sh - 1)) & 1u) * ONE;
            v.z = ((wr >> (sh - 2)) & 1u) * ONE;
            v.w = ((wr >> (sh - 3)) & 1u) * ONE;
        }
        gout[k * 32 + lane] = v;
    }
}

// Generic tail path: one thread per 16B output chunk (redundant row decode).
__global__ void fp8_tail_kernel(const uint4* __restrict__ in,
                                uint4* __restrict__ out, int nchunks)
{
    int idx = blockIdx.x * blockDim.x + threadIdx.x;
    if (idx >= nchunks) return;
    int row  = idx >> 3;
    int part = idx & 7;
    uint32_t w = fp32_word(in[2 * row], in[2 * row + 1]);
    const uint32_t ONE = 0x3F800000u;
    uint4 v = make_uint4(0u, 0u, 0u, 0u);
    if (part < 3) {
        int sh = 31 - part * 4;
        v.x = ((w >> sh)       & 1u) * ONE;
        v.y = ((w >> (sh - 1)) & 1u) * ONE;
        v.z = ((w >> (sh - 2)) & 1u) * ONE;
        v.w = ((w >> (sh - 3)) & 1u) * ONE;
    }
    out[idx] = v;
}

extern "C" void kernel_launch(void* const* d_in, const int* in_sizes, int n_in,
                              void* d_out, int out_size)
{
    const uint4* in  = (const uint4*)d_in[0];
    uint4*       out = (uint4*)d_out;
    int nrows = in_sizes[0] / 8;              // 4194304

    int fullBlocks = nrows / RPB;             // 16384
    int remRows    = nrows % RPB;

    if (fullBlocks > 0)
        fp8_full_kernel<<<fullBlocks, TPB>>>(in, out);
    if (remRows > 0) {
        int nchunks = remRows * 8;
        fp8_tail_kernel<<<(nchunks + TPB - 1) / TPB, TPB>>>(
            in + (size_t)fullBlocks * RPB * 2,
            out + (size_t)fullBlocks * RPB * 8,
            nchunks);
    }
}

// round 6
// speedup vs baseline: 1.0027x; 1.0003x over previous
#include <cuda_runtime.h>
#include <cstdint>

// FP8 (E4M3 bit-vector of 0.0/1.0 floats) -> FP32 bit-vector.
// In : 4194304 rows x 8 floats  [s, e3, e2, e1, e0, m2, m1, m0]
// Out: 4194304 rows x 32 floats [s, exp7..exp0, mant22..mant0]
// Only outputs 0..11 per row can be nonzero.
//
// R6: restore the best structure (R3: smem-staged, 256 rows/block, fully
// coalesced loads and stores) + evict-first hint on the read-once input
// stream so it doesn't churn L2 against the 4x larger write stream.

#define TPB 256   // threads per block == rows per block

__device__ __forceinline__ uint32_t fp32_word(uint4 A, uint4 B)
{
    // 1.0f == 0x3F800000 -> test bit 29.
    uint32_t s = (A.x >> 29) & 1u;
    uint32_t e = ((A.y >> 26) & 8u) | ((A.z >> 27) & 4u) |
                 ((A.w >> 28) & 2u) | ((B.x >> 29) & 1u);
    uint32_t m = ((B.y >> 27) & 4u) | ((B.z >> 28) & 2u) |
                 ((B.w >> 29) & 1u);

    uint32_t expf, mant;
    if (e != 0u) {                 // normal (incl. NaN pattern, as reference)
        expf = e + 120u;
        mant = m << 20;
    } else if (m & 4u) {           // subnormal 1xx
        expf = 120u;
        mant = (m & 3u) << 21;
    } else if (m & 2u) {           // subnormal 01x
        expf = 119u;
        mant = (m & 1u) << 22;
    } else if (m != 0u) {          // subnormal 001
        expf = 118u;
        mant = 0u;
    } else {                       // true zero
        expf = 0u;
        mant = 0u;
    }
    return (s << 31) | (expf << 23) | mant;   // bits 19..0 == 0
}

template <bool FULL>
__global__ void __launch_bounds__(TPB)
fp8_to_fp32_bits_kernel(const uint4* __restrict__ in,
                        uint4* __restrict__ out,
                        int nrows)
{
    __shared__ uint4    s_in[2 * TPB];   // 256 rows x 32B = 8KB
    __shared__ uint32_t s_w[TPB];        // one fp32 bit-word per row

    const int t = threadIdx.x;
    const size_t rowBase = (size_t)blockIdx.x * TPB;
    const int rowsHere = FULL ? TPB : min(TPB, nrows - (int)rowBase);

    // ---- Phase 1: coalesced, evict-first global loads into smem ----
    const uint4* gin = in + rowBase * 2;
    if (FULL || t < 2 * rowsHere)        s_in[t]       = __ldcs(&gin[t]);
    if (FULL || t + TPB < 2 * rowsHere)  s_in[t + TPB] = __ldcs(&gin[t + TPB]);
    __syncthreads();

    // ---- Phase 2: one thread per row computes the fp32 bit word ----
    if (FULL || t < rowsHere)
        s_w[t] = fp32_word(s_in[2 * t], s_in[2 * t + 1]);
    __syncthreads();

    // ---- Phase 3: coalesced global stores (contiguous 32KB per block) ----
    uint4* gout = out + rowBase * 8;
    const uint32_t ONE = 0x3F800000u;
    const int chunksHere = 8 * rowsHere;

    #pragma unroll
    for (int k = 0; k < 8; k++) {
        int idx  = k * TPB + t;
        if (!FULL && idx >= chunksHere) break;
        int row  = idx >> 3;           // which row this 16B chunk belongs to
        int part = idx & 7;            // which of the 8 chunks in the row
        uint4 v = make_uint4(0u, 0u, 0u, 0u);
        if (part < 3) {
            uint32_t w  = s_w[row];    // broadcast across the 8 lanes of a row
            int sh = 31 - part * 4;    // chunk0: 31..28, chunk1: 27..24, chunk2: 23..20
            v.x = ((w >> sh)       & 1u) * ONE;
            v.y = ((w >> (sh - 1)) & 1u) * ONE;
            v.z = ((w >> (sh - 2)) & 1u) * ONE;
            v.w = ((w >> (sh - 3)) & 1u) * ONE;
        }
        gout[idx] = v;
    }
}

extern "C" void kernel_launch(void* const* d_in, const int* in_sizes, int n_in,
                              void* d_out, int out_size)
{
    const uint4* in  = (const uint4*)d_in[0];
    uint4*       out = (uint4*)d_out;
    int nrows = in_sizes[0] / 8;              // 4194304

    int fullBlocks = nrows / TPB;             // 16384
    int remRows    = nrows % TPB;

    if (fullBlocks > 0)
        fp8_to_fp32_bits_kernel<true><<<fullBlocks, TPB>>>(in, out, nrows);
    if (remRows > 0)
        fp8_to_fp32_bits_kernel<false><<<1, TPB>>>(
            in + (size_t)fullBlocks * TPB * 2,
            out + (size_t)fullBlocks * TPB * 8,
            remRows);
}

// round 8
// speedup vs baseline: 1.0155x; 1.0128x over previous
#include <cuda_runtime.h>
#include <cstdint>

// FP8 (E4M3 bit-vector of 0.0/1.0 floats) -> FP32 bit-vector.
// In : 4194304 rows x 8 floats  [s, e3, e2, e1, e0, m2, m1, m0]
// Out: 4194304 rows x 32 floats [s, exp7..exp0, mant22..mant0]
// Only outputs 0..11 per row can be nonzero.
//
// FINAL (R3 structure, best measured 104.5us): stage through shared memory so
// both global loads and global stores are fully coalesced (consecutive lanes
// -> consecutive 16B chunks). DRAM-bound at ~6.1 TB/s; structural variants
// R3-R6 all measured within noise, so this is the converged configuration.

#define TPB 256   // threads per block == rows per block

__device__ __forceinline__ uint32_t fp32_word(uint4 A, uint4 B)
{
    // 1.0f == 0x3F800000 -> test bit 29.
    uint32_t s = (A.x >> 29) & 1u;
    uint32_t e = ((A.y >> 26) & 8u) | ((A.z >> 27) & 4u) |
                 ((A.w >> 28) & 2u) | ((B.x >> 29) & 1u);
    uint32_t m = ((B.y >> 27) & 4u) | ((B.z >> 28) & 2u) |
                 ((B.w >> 29) & 1u);

    uint32_t expf, mant;
    if (e != 0u) {                 // normal (incl. NaN pattern, as reference)
        expf = e + 120u;
        mant = m << 20;
    } else if (m & 4u) {           // subnormal 1xx
        expf = 120u;
        mant = (m & 3u) << 21;
    } else if (m & 2u) {           // subnormal 01x
        expf = 119u;
        mant = (m & 1u) << 22;
    } else if (m != 0u) {          // subnormal 001
        expf = 118u;
        mant = 0u;
    } else {                       // true zero
        expf = 0u;
        mant = 0u;
    }
    return (s << 31) | (expf << 23) | mant;   // bits 19..0 == 0
}

template <bool FULL>
__global__ void __launch_bounds__(TPB)
fp8_to_fp32_bits_kernel(const uint4* __restrict__ in,
                        uint4* __restrict__ out,
                        int nrows)
{
    __shared__ uint4    s_in[2 * TPB];   // 256 rows x 32B = 8KB
    __shared__ uint32_t s_w[TPB];        // one fp32 bit-word per row

    const int t = threadIdx.x;
    const size_t rowBase = (size_t)blockIdx.x * TPB;
    const int rowsHere = FULL ? TPB : min(TPB, nrows - (int)rowBase);

    // ---- Phase 1: coalesced global loads into smem (contiguous 8KB) ----
    const uint4* gin = in + rowBase * 2;
    if (FULL || t < 2 * rowsHere)        s_in[t]       = gin[t];
    if (FULL || t + TPB < 2 * rowsHere)  s_in[t + TPB] = gin[t + TPB];
    __syncthreads();

    // ---- Phase 2: one thread per row computes the fp32 bit word ----
    if (FULL || t < rowsHere)
        s_w[t] = fp32_word(s_in[2 * t], s_in[2 * t + 1]);
    __syncthreads();

    // ---- Phase 3: coalesced global stores (contiguous 32KB per block) ----
    uint4* gout = out + rowBase * 8;
    const uint32_t ONE = 0x3F800000u;
    const int chunksHere = 8 * rowsHere;

    #pragma unroll
    for (int k = 0; k < 8; k++) {
        int idx  = k * TPB + t;
        if (!FULL && idx >= chunksHere) break;
        int row  = idx >> 3;           // which row this 16B chunk belongs to
        int part = idx & 7;            // which of the 8 chunks in the row
        uint4 v = make_uint4(0u, 0u, 0u, 0u);
        if (part < 3) {
            uint32_t w  = s_w[row];    // broadcast across the 8 lanes of a row
            int sh = 31 - part * 4;    // chunk0: 31..28, chunk1: 27..24, chunk2: 23..20
            v.x = ((w >> sh)       & 1u) * ONE;
            v.y = ((w >> (sh - 1)) & 1u) * ONE;
            v.z = ((w >> (sh - 2)) & 1u) * ONE;
            v.w = ((w >> (sh - 3)) & 1u) * ONE;
        }
        gout[idx] = v;
    }
}

extern "C" void kernel_launch(void* const* d_in, const int* in_sizes, int n_in,
                              void* d_out, int out_size)
{
    const uint4* in  = (const uint4*)d_in[0];
    uint4*       out = (uint4*)d_out;
    int nrows = in_sizes[0] / 8;              // 4194304

    int fullBlocks = nrows / TPB;             // 16384
    int remRows    = nrows % TPB;

    if (fullBlocks > 0)
        fp8_to_fp32_bits_kernel<true><<<fullBlocks, TPB>>>(in, out, nrows);
    if (remRows > 0)
        fp8_to_fp32_bits_kernel<false><<<1, TPB>>>(
            in + (size_t)fullBlocks * TPB * 2,
            out + (size_t)fullBlocks * TPB * 8,
            remRows);
}